// round 11
// baseline (speedup 1.0000x reference)
#include <cuda_runtime.h>
#include <cuda_fp16.h>
#include <math.h>
#include <stdint.h>

#define BB   4
#define NN   10000
#define EE   100000
#define CIN  16
#define NF   128
#define WN   384
#define OUTD 40
#define ALPHA_C 0.25f
#define BN_EPS_C 1e-5f
#define M_TOT 40000.0f
#define KPAD 136                 // fp16 smem row stride (272B, ldmatrix conflict-free)
#define TROW 3104                // T row stride (halfs): 3072 data + 24 bias + 8 pad
#define TDATA 3096
#define NT2 (TDATA/2)            // 1548 half2 per T row
#define NTILES 782               // ceil(EE/128)

// ---- edge-kernel smem offsets (bytes) ----
#define OFF_A    0               // 128*KPAD halfs = 34816
#define OFF_W    34816           // 128*KPAD halfs = 34816
#define OFF_TT   69632           // 2 x 24*132 halfs = 12672
#define OFF_BIAS 82304           // 2 x 24 f32 = 192
#define OFF_EID  82496           // 128 int
#define OFF_SRC  83008
#define OFF_DST  83520
#define OFF_SH   84032           // 128 float4 = 2048
#define OFF_RST  86080           // 129 int -> 520
#define OFF_UQN  86600           // 128 int
#define OFF_WCNT 87112           // 4 int
#define OFF_NU   87128           // 1 int
#define SMEM_EDGE 87136

// ---------------- device scratch ---------------------------------------------
__device__ float g_xnew[BB*NN*CIN];
__device__ float g_agg[BB*NN*OUTD];
__device__ float g_cnt[NN];
__device__ float g_sum[OUTD];
__device__ float g_sumsq[OUTD];
__device__ int   g_scnt[NN];
__device__ int   g_soff[NN+1];
__device__ int   g_spos[NN];
__device__ int   g_sedge[EE];
__device__ __align__(16) __half g_w1t[NF*NF];          // [n][k] fp16
__device__ __align__(16) __half g_w2pt[TROW*16];       // W2p transposed: [j][i]
__device__ __align__(16) __half g_Th[(size_t)BB*NN*TROW];  // 248 MB fp16 T

// ---------------- zero scratch -----------------------------------------------
__global__ void zero_kernel() {
    int i = blockIdx.x * blockDim.x + threadIdx.x;
    if (i < BB*NN*OUTD) g_agg[i] = 0.0f;
    if (i < NN) { g_cnt[i] = 0.0f; g_scnt[i] = 0; }
    if (i < OUTD) { g_sum[i] = 0.0f; g_sumsq[i] = 0.0f; }
}

// ---------------- W1 transpose -> fp16 ---------------------------------------
__global__ void prep1_kernel(const float* __restrict__ w1) {
    int idx = blockIdx.x * blockDim.x + threadIdx.x;
    if (idx < NF*NF) {
        int n = idx / NF, k = idx % NF;
        g_w1t[idx] = __float2half_rn(w1[k*NF + n]);
    }
}

// ---------------- W2pT build: g_w2pt[j*16+i] ---------------------------------
// j<3072: k=j/24, o=j%24, col = o<16 ? i*16+o : 256+i*8+(o-16); val = w2[k][col]
// j in [3072,3096): o=j-3072 -> b2[col]; else 0
__global__ void prep2_kernel(const float* __restrict__ w2,
                             const float* __restrict__ b2) {
    int idx = blockIdx.x * blockDim.x + threadIdx.x;
    if (idx >= TROW*16) return;
    int j = idx >> 4, i = idx & 15;
    float v = 0.f;
    if (j < 3072) {
        int k = j / 24, o = j % 24;
        int col = (o < 16) ? (i*16 + o) : (256 + i*8 + (o - 16));
        v = w2[k*WN + col];
    } else if (j < TDATA) {
        int o = j - 3072;
        int col = (o < 16) ? (i*16 + o) : (256 + i*8 + (o - 16));
        v = b2[col];
    }
    g_w2pt[idx] = __float2half_rn(v);
}

// ---------------- closed-form FFT time mixing (proven) -----------------------
__global__ void xnew_kernel(const float* __restrict__ x,
                            const float* __restrict__ wr,
                            const float* __restrict__ wi) {
    __shared__ float sWr[CIN][CIN];
    __shared__ float sWi[CIN][CIN];
    int t = threadIdx.x;
    {
        int i = t >> 4, o = t & 15;
        sWr[i][o] = wr[i*32 + o*2 + 0] + wr[i*32 + o*2 + 1];
        sWi[i][o] = wi[i*32 + o*2 + 0] + wi[i*32 + o*2 + 1];
    }
    __syncthreads();
    int idx = blockIdx.x * blockDim.x + t;
    if (idx >= NN*CIN) return;
    int n = idx >> 4, o = idx & 15;
    float x0r = 0.f, re1 = 0.f, im1 = 0.f;
    #pragma unroll
    for (int i = 0; i < CIN; i++) {
        float a0 = x[(0*NN + n)*CIN + i];
        float a1 = x[(1*NN + n)*CIN + i];
        float a2 = x[(2*NN + n)*CIN + i];
        float a3 = x[(3*NN + n)*CIN + i];
        float S = a0 + a1 + a2 + a3;
        float P = a0 - a2;
        float Q = a3 - a1;
        float wrv = sWr[i][o], wiv = sWi[i][o];
        x0r += S * wrv;
        re1 += P * wrv - Q * wiv;
        im1 += P * wiv + Q * wrv;
    }
    g_xnew[(0*NN + n)*CIN + o] = 0.25f*(x0r + 2.f*re1);
    g_xnew[(1*NN + n)*CIN + o] = 0.25f*(x0r - 2.f*im1);
    g_xnew[(2*NN + n)*CIN + o] = 0.25f*(x0r - 2.f*re1);
    g_xnew[(3*NN + n)*CIN + o] = 0.25f*(x0r + 2.f*im1);
}

// ---------------- degree counts (dst for mean, src for sort) -----------------
__global__ void count_kernel(const int* __restrict__ eidx) {
    int e = blockIdx.x * blockDim.x + threadIdx.x;
    if (e < EE) {
        atomicAdd(&g_cnt[eidx[EE + e]], 1.0f);
        atomicAdd(&g_scnt[eidx[e]], 1);
    }
}

// ---------------- single-block exclusive scan (proven R8) --------------------
__global__ void scan_kernel() {
    __shared__ int part[256];
    int t = threadIdx.x;
    int n0 = t * 40;
    int n1 = min(n0 + 40, NN);
    int s = 0;
    for (int i = n0; i < n1; i++) s += g_scnt[i];
    part[t] = s;
    __syncthreads();
    for (int off = 1; off < 256; off <<= 1) {
        int v = 0;
        if (t >= off) v = part[t - off];
        __syncthreads();
        part[t] += v;
        __syncthreads();
    }
    int run = (t == 0) ? 0 : part[t - 1];
    for (int i = n0; i < n1; i++) {
        g_soff[i] = run;
        g_spos[i] = run;
        run += g_scnt[i];
    }
    if (t == 0) g_soff[NN] = EE;
}

__global__ void scatter_kernel(const int* __restrict__ eidx) {
    int e = blockIdx.x * blockDim.x + threadIdx.x;
    if (e < EE) {
        int p = atomicAdd(&g_spos[eidx[e]], 1);
        g_sedge[p] = e;
    }
}

// ---------------- mma.sync fp16 helpers (proven R9) --------------------------
__device__ __forceinline__ void mma_f16(float* c, const unsigned* a, const unsigned* b) {
    asm volatile(
        "mma.sync.aligned.m16n8k16.row.col.f32.f16.f16.f32 "
        "{%0,%1,%2,%3}, {%4,%5,%6,%7}, {%8,%9}, {%0,%1,%2,%3};\n"
        : "+f"(c[0]), "+f"(c[1]), "+f"(c[2]), "+f"(c[3])
        : "r"(a[0]), "r"(a[1]), "r"(a[2]), "r"(a[3]), "r"(b[0]), "r"(b[1]));
}
__device__ __forceinline__ void ldmat4(unsigned* a, const __half* p) {
    unsigned addr = (unsigned)__cvta_generic_to_shared(p);
    asm volatile("ldmatrix.sync.aligned.m8n8.x4.shared.b16 {%0,%1,%2,%3}, [%4];"
                 : "=r"(a[0]), "=r"(a[1]), "=r"(a[2]), "=r"(a[3]) : "r"(addr));
}
__device__ __forceinline__ unsigned packh2(float a, float b) {
    __half2 t;
    t.x = __float2half_rn(a);
    t.y = __float2half_rn(b);
    return *reinterpret_cast<unsigned*>(&t);
}

// single-term fp16 GEMM (proven R9): acc += A@W^T (M=128,N=128,K=128)
__device__ __forceinline__ void gemm_f16(
    const __half* __restrict__ sA, const __half* __restrict__ sW,
    int warp, int lane, float acc[8][2][4])
{
    const __half* Arow = sA + (lane & 15)*KPAD + (lane >> 4)*8;
    const __half* Wb = sW + (warp*16 + (lane >> 2))*KPAD + (lane & 3)*2;
    #pragma unroll
    for (int k0 = 0; k0 < 128; k0 += 16) {
        unsigned b0[2], b1[2];
        b0[0] = *(const unsigned*)&Wb[k0];
        b0[1] = *(const unsigned*)&Wb[k0 + 8];
        b1[0] = *(const unsigned*)&Wb[8*KPAD + k0];
        b1[1] = *(const unsigned*)&Wb[8*KPAD + k0 + 8];
        #pragma unroll
        for (int mt = 0; mt < 8; mt++) {
            unsigned a[4];
            ldmat4(a, Arow + mt*16*KPAD + k0);
            mma_f16(acc[mt][0], a, b0);
            mma_f16(acc[mt][1], a, b1);
        }
    }
}

// ---------------- T build: g_Th[node] = xnew[node] @ W2p (tensor) ------------
__global__ __launch_bounds__(256)
void tbuild_kernel() {
    __shared__ __half sA[128*24];
    __shared__ __half sBT[128*24];
    __shared__ __half sC[128*136];
    const int tid = threadIdx.x;
    const int warp = tid >> 5, lane = tid & 31;
    const int bn0 = blockIdx.x * 128;

    // stage xnew rows (fp32 -> fp16), stride 24 halfs (48B, ldmatrix-clean)
    {
        int row = tid >> 1, i8 = (tid & 1) * 8;
        int node = bn0 + row;
        if (node >= BB*NN) node = 0;
        const float* src = &g_xnew[(size_t)node*CIN + i8];
        float4 v0 = *(const float4*)&src[0];
        float4 v1 = *(const float4*)&src[4];
        __half2* d = (__half2*)&sA[row*24 + i8];
        d[0] = __floats2half2_rn(v0.x, v0.y);
        d[1] = __floats2half2_rn(v0.z, v0.w);
        d[2] = __floats2half2_rn(v1.x, v1.y);
        d[3] = __floats2half2_rn(v1.z, v1.w);
    }
    __syncthreads();
    unsigned afrag[4];
    ldmat4(afrag, (const __half*)sA + (warp*16 + (lane & 15))*24 + (lane >> 4)*8);

    for (int ch = 0; ch < 25; ch++) {
        __syncthreads();
        // stage W2pT chunk cols [ch*128, +128)
        {
            int n = tid >> 1, i8 = (tid & 1) * 8;
            int col = ch*128 + n;
            float4 v = make_float4(0.f, 0.f, 0.f, 0.f);
            if (col < TROW) v = *(const float4*)&g_w2pt[col*16 + i8];
            *(float4*)&sBT[n*24 + i8] = v;
        }
        __syncthreads();
        #pragma unroll
        for (int n8 = 0; n8 < 16; n8++) {
            float c[4] = {0.f, 0.f, 0.f, 0.f};
            const __half* Wb = sBT + (n8*8 + (lane >> 2))*24 + (lane & 3)*2;
            unsigned b[2];
            b[0] = *(const unsigned*)&Wb[0];
            b[1] = *(const unsigned*)&Wb[8];
            mma_f16(c, afrag, b);
            int r0 = warp*16 + (lane >> 2);
            int c0 = n8*8 + (lane & 3)*2;
            *(__half2*)&sC[r0*136 + c0]       = *(__half2*)&(unsigned&)(*(unsigned*)&c[0]) , // placeholder
            *(__half2*)&sC[r0*136 + c0]       = __floats2half2_rn(c[0], c[1]);
            *(__half2*)&sC[(r0+8)*136 + c0]   = __floats2half2_rn(c[2], c[3]);
        }
        __syncthreads();
        // coalesced store sC -> g_Th
        #pragma unroll
        for (int w = 0; w < 8; w++) {
            int it = tid + w*256;              // 0..2047
            int row = it >> 4, c16 = it & 15;
            int node = bn0 + row;
            int j = ch*128 + c16*8;
            if (node < BB*NN && j + 8 <= TROW) {
                float4 v = *(const float4*)&sC[row*136 + c16*8];
                *(float4*)&g_Th[(size_t)node*TROW + j] = v;
            }
        }
    }
}

// ---------------- fused edge kernel: gather + GEMM1 + T-contract + scatter ---
__global__ __launch_bounds__(256, 2)
void edge_fused_kernel(const float* __restrict__ ea, const float* __restrict__ b1g,
                       const int* __restrict__ eidx, const float* __restrict__ esh)
{
    extern __shared__ char smem[];
    __half* sA   = (__half*)(smem + OFF_A);
    __half* sW   = (__half*)(smem + OFF_W);
    int*    sEid = (int*)(smem + OFF_EID);
    int*    sSrc = (int*)(smem + OFF_SRC);
    int*    sDst = (int*)(smem + OFF_DST);
    float4* sSh  = (float4*)(smem + OFF_SH);
    int*    sRst = (int*)(smem + OFF_RST);
    int*    sUqn = (int*)(smem + OFF_UQN);
    int*    sWcnt= (int*)(smem + OFF_WCNT);
    int*    sNu  = (int*)(smem + OFF_NU);

    const int tid = threadIdx.x;
    const int warp = tid >> 5, lane = tid & 31;
    const int t  = blockIdx.x;
    const int bb = blockIdx.y;
    const int ne = min(128, EE - t*128);

    // ---- phase A: edge metadata ----
    if (tid < 128) {
        int j = tid;
        int p = t*128 + min(j, ne - 1);
        int e = g_sedge[p];
        sEid[j] = e;
        sSrc[j] = eidx[e];
        sDst[j] = eidx[EE + e];
        sSh[j]  = *(const float4*)&esh[((size_t)bb*EE + e)*4];
    }
    __syncthreads();

    // ---- range flags (warps 0-3 only) ----
    int fl = 0, wpc = 0;
    if (tid < 128) {
        int j = tid;
        fl = (j < ne) && (j == 0 || sSrc[j] != sSrc[j-1]);
        unsigned mask = __ballot_sync(0xffffffffu, fl);
        wpc = __popc(mask & ((1u << lane) - 1u));
        if (lane == 31) sWcnt[warp] = __popc(mask);
    }

    // ---- gather A rows by edge id (fp32 -> fp16) ----
    #pragma unroll
    for (int tt2 = 0; tt2 < 16; tt2++) {
        int idx = tid + tt2*256;
        int r = idx >> 5, q = (idx & 31) << 2;
        int e = sEid[r];
        float4 v = *(const float4*)&ea[((size_t)bb*EE + e)*NF + q];
        uint2 u = make_uint2(packh2(v.x, v.y), packh2(v.z, v.w));
        *(uint2*)&sA[r*KPAD + q] = u;
    }
    // ---- stage W1T ----
    #pragma unroll
    for (int tt2 = 0; tt2 < 8; tt2++) {
        int idx = tid + tt2*256;
        int n = idx >> 4, q = (idx & 15) << 3;
        *(float4*)&sW[n*KPAD + q] = *(const float4*)&g_w1t[n*NF + q];
    }
    __syncthreads();

    // ---- finish range build ----
    if (tid < 128) {
        int base = 0;
        #pragma unroll
        for (int w = 0; w < 4; w++) if (w < warp) base += sWcnt[w];
        if (fl) { sUqn[base + wpc] = sSrc[tid]; sRst[base + wpc] = tid; }
        if (tid == 0) {
            int nu = sWcnt[0] + sWcnt[1] + sWcnt[2] + sWcnt[3];
            sNu[0] = nu;
            sRst[nu] = ne;
        }
    }

    // ---- GEMM1: H = relu(A@W1 + b1) ----
    float acc[8][2][4];
    {
        int colb = warp*16 + (lane & 3)*2;
        #pragma unroll
        for (int nt = 0; nt < 2; nt++) {
            float bc0 = b1g[colb + nt*8], bc1 = b1g[colb + nt*8 + 1];
            #pragma unroll
            for (int mt = 0; mt < 8; mt++) {
                acc[mt][nt][0] = bc0; acc[mt][nt][1] = bc1;
                acc[mt][nt][2] = bc0; acc[mt][nt][3] = bc1;
            }
        }
    }
    gemm_f16(sA, sW, warp, lane, acc);
    __syncthreads();

    // ---- relu -> fp16 H back into sA ----
    {
        int c0 = warp*16 + (lane & 3)*2;
        int r0 = lane >> 2;
        #pragma unroll
        for (int mt = 0; mt < 8; mt++) {
            #pragma unroll
            for (int nt = 0; nt < 2; nt++) {
                int col = c0 + nt*8;
                #pragma unroll
                for (int half = 0; half < 2; half++) {
                    int row = mt*16 + r0 + half*8;
                    float h0 = fmaxf(acc[mt][nt][half*2 + 0], 0.f);
                    float h1 = fmaxf(acc[mt][nt][half*2 + 1], 0.f);
                    *(unsigned*)&sA[row*KPAD + col] = packh2(h0, h1);
                }
            }
        }
    }
    __syncthreads();   // h + ranges visible

    // ---- contraction: per distinct src node, double-buffered T staging ----
    const int nu = sNu[0];
    __half* ttb  = (__half*)(smem + OFF_TT);
    float* biasb = (float*)(smem + OFF_BIAS);
    unsigned pv[7];
    {
        size_t basep = ((size_t)bb*NN + sUqn[0])*TROW;
        #pragma unroll
        for (int it = 0; it < 7; it++) {
            int i2 = tid + it*256;
            if (i2 < NT2) pv[it] = *(const unsigned*)&g_Th[basep + (size_t)i2*2];
        }
    }
    for (int u = 0; u < nu; u++) {
        __half* tt  = ttb + (u & 1)*(24*132);
        float* bias = biasb + (u & 1)*24;
        // write staged row (transpose [k*24+o] -> [o][k], bias split)
        #pragma unroll
        for (int it = 0; it < 7; it++) {
            int i2 = tid + it*256;
            if (i2 < NT2) {
                __half2 hv = *(__half2*)&pv[it];
                int j0 = i2*2;
                if (j0 < 3072) tt[(j0 % 24)*132 + j0/24] = __low2half(hv);
                else           bias[j0 - 3072] = __half2float(__low2half(hv));
                int j1 = j0 + 1;
                if (j1 < 3072) tt[(j1 % 24)*132 + j1/24] = __high2half(hv);
                else           bias[j1 - 3072] = __half2float(__high2half(hv));
            }
        }
        __syncthreads();
        // prefetch next node's T row (latency hidden by compute)
        if (u + 1 < nu) {
            size_t basep = ((size_t)bb*NN + sUqn[u+1])*TROW;
            #pragma unroll
            for (int it = 0; it < 7; it++) {
                int i2 = tid + it*256;
                if (i2 < NT2) pv[it] = *(const unsigned*)&g_Th[basep + (size_t)i2*2];
            }
        }
        // tasks: (edge-in-range, o)
        int jb = sRst[u], je = sRst[u+1];
        int cnt = (je - jb)*24;
        for (int task = tid; task < cnt; task += 256) {
            int eo = task / 24, o = task - eo*24;
            int eloc = jb + eo;
            const __half* hrow = sA + eloc*KPAD;
            const __half* trow = tt + o*132;
            float accf = bias[o];
            #pragma unroll
            for (int c = 0; c < 8; c++) {
                __half2 s = __float2half2_rn(0.f);
                #pragma unroll
                for (int q = 0; q < 8; q++) {
                    int k2 = c*8 + q;
                    s = __hfma2(*(const __half2*)&hrow[k2*2],
                                *(const __half2*)&trow[k2*2], s);
                }
                float2 f = __half22float2(s);
                accf += f.x + f.y;
            }
            float4 sh = sSh[eloc];
            float* aggp = &g_agg[((size_t)bb*NN + sDst[eloc])*OUTD];
            if (o < 16) {
                atomicAdd(&aggp[o], ALPHA_C * sh.x * accf);
            } else {
                int c3 = o - 16;
                float v = ALPHA_C * accf;
                atomicAdd(&aggp[16 + c3*3 + 0], v * sh.y);
                atomicAdd(&aggp[16 + c3*3 + 1], v * sh.z);
                atomicAdd(&aggp[16 + c3*3 + 2], v * sh.w);
            }
        }
    }
}

// ---------------- mean-by-count + BN stats (proven) --------------------------
__global__ void stats_kernel() {
    int row = blockIdx.x * blockDim.x + threadIdx.x;
    float v[OUTD];
    if (row < BB*NN) {
        int n = row % NN;
        float inv = 1.0f / fmaxf(g_cnt[n], 1.0f);
        float4* p = (float4*)&g_agg[row*OUTD];
        #pragma unroll
        for (int t = 0; t < 10; t++) {
            float4 a = p[t];
            a.x *= inv; a.y *= inv; a.z *= inv; a.w *= inv;
            p[t] = a;
            v[t*4+0] = a.x; v[t*4+1] = a.y; v[t*4+2] = a.z; v[t*4+3] = a.w;
        }
    } else {
        #pragma unroll
        for (int c = 0; c < OUTD; c++) v[c] = 0.f;
    }
    #pragma unroll
    for (int c = 0; c < OUTD; c++) {
        float s = v[c], q = v[c]*v[c];
        #pragma unroll
        for (int off = 16; off > 0; off >>= 1) {
            s += __shfl_down_sync(0xffffffffu, s, off);
            q += __shfl_down_sync(0xffffffffu, q, off);
        }
        if ((threadIdx.x & 31) == 0) {
            atomicAdd(&g_sum[c],   s);
            atomicAdd(&g_sumsq[c], q);
        }
    }
}

__global__ void norm_kernel(float* __restrict__ out,
                            const float* __restrict__ gamma,
                            const float* __restrict__ beta) {
    int i = blockIdx.x * blockDim.x + threadIdx.x;
    if (i >= BB*NN*OUTD) return;
    int c = i % OUTD;
    const float invM = 1.0f / M_TOT;
    float mu  = g_sum[c] * invM;
    float var = g_sumsq[c] * invM - mu*mu;
    out[i] = (g_agg[i] - mu) * rsqrtf(var + BN_EPS_C) * gamma[c] + beta[c];
}

// ---------------- launch ------------------------------------------------------
extern "C" void kernel_launch(void* const* d_in, const int* in_sizes, int n_in,
                              void* d_out, int out_size) {
    const float* x     = (const float*)d_in[0];
    const int*   eidx  = (const int*)  d_in[1];
    const float* ea    = (const float*)d_in[2];
    const float* esh   = (const float*)d_in[3];
    const float* wr    = (const float*)d_in[4];
    const float* wi    = (const float*)d_in[5];
    const float* w1    = (const float*)d_in[6];
    const float* b1    = (const float*)d_in[7];
    const float* w2    = (const float*)d_in[8];
    const float* b2    = (const float*)d_in[9];
    const float* gamma = (const float*)d_in[10];
    const float* beta  = (const float*)d_in[11];
    float* out = (float*)d_out;

    cudaFuncSetAttribute(edge_fused_kernel,
                         cudaFuncAttributeMaxDynamicSharedMemorySize, SMEM_EDGE);

    zero_kernel   <<<(BB*NN*OUTD + 255)/256, 256>>>();
    xnew_kernel   <<<(NN*CIN + 255)/256, 256>>>(x, wr, wi);
    count_kernel  <<<(EE + 255)/256, 256>>>(eidx);
    scan_kernel   <<<1, 256>>>();
    scatter_kernel<<<(EE + 255)/256, 256>>>(eidx);
    prep1_kernel  <<<(NF*NF + 255)/256, 256>>>(w1);
    prep2_kernel  <<<(TROW*16 + 255)/256, 256>>>(w2, b2);
    tbuild_kernel <<<(BB*NN + 127)/128, 256>>>();
    {
        dim3 grid(NTILES, BB);
        edge_fused_kernel<<<grid, 256, SMEM_EDGE>>>(ea, b1, eidx, esh);
    }
    stats_kernel  <<<(BB*NN + 255)/256, 256>>>();
    norm_kernel   <<<(BB*NN*OUTD + 255)/256, 256>>>(out, gamma, beta);
}

// round 14
// speedup vs baseline: 1.4529x; 1.4529x over previous
#include <cuda_runtime.h>
#include <cuda_fp16.h>
#include <math.h>

#define BB   4
#define NN   10000
#define EE   100000
#define CIN  16
#define NF   128
#define WN   384
#define OUTD 40
#define MROWS (BB*EE)            // 400000
#define ALPHA_C 0.25f
#define BN_EPS_C 1e-5f
#define M_TOT 40000.0f
#define KPAD 136                 // fp16 smem row stride (272B, ldmatrix conflict-free)
#define EWP  134                 // fp16 sEw row stride (halfs)
#define OFF_A  0                 // 128*KPAD halfs = 34816 B
#define OFF_W  34816             // 128*KPAD halfs = 34816 B
#define OFF_EW 69632             // 128*EWP halfs = 34304 B
#define SMEM_BYTES 103936        // -> 2 CTAs/SM

// ---------------- device scratch ---------------------------------------------
__device__ float g_xnew[BB*NN*CIN];
__device__ float g_agg[BB*NN*OUTD];
__device__ float g_cnt[NN];
__device__ float g_sum[OUTD];
__device__ float g_sumsq[OUTD];
__device__ __align__(16) __half g_w1t[NF*NF];   // [n][k] transposed fp16
__device__ __align__(16) __half g_w2t[WN*NF];   // [n][k] transposed fp16

// ---------------- zero scratch -----------------------------------------------
__global__ void zero_kernel() {
    int i = blockIdx.x * blockDim.x + threadIdx.x;
    if (i < BB*NN*OUTD) g_agg[i] = 0.0f;
    if (i < NN)         g_cnt[i] = 0.0f;
    if (i < OUTD) { g_sum[i] = 0.0f; g_sumsq[i] = 0.0f; }
}

// ---------------- weight transpose -> fp16 -----------------------------------
__global__ void prep_kernel(const float* __restrict__ w1,
                            const float* __restrict__ w2) {
    int idx = blockIdx.x * blockDim.x + threadIdx.x;
    if (idx < NF*NF) {
        int n = idx / NF, k = idx % NF;
        g_w1t[idx] = __float2half_rn(w1[k*NF + n]);
    }
    if (idx < WN*NF) {
        int n = idx / NF, k = idx % NF;
        g_w2t[idx] = __float2half_rn(w2[k*WN + n]);
    }
}

// ---------------- closed-form FFT time mixing (proven) -----------------------
__global__ void xnew_kernel(const float* __restrict__ x,
                            const float* __restrict__ wr,
                            const float* __restrict__ wi) {
    __shared__ float sWr[CIN][CIN];
    __shared__ float sWi[CIN][CIN];
    int t = threadIdx.x;
    {
        int i = t >> 4, o = t & 15;
        sWr[i][o] = wr[i*32 + o*2 + 0] + wr[i*32 + o*2 + 1];
        sWi[i][o] = wi[i*32 + o*2 + 0] + wi[i*32 + o*2 + 1];
    }
    __syncthreads();
    int idx = blockIdx.x * blockDim.x + t;
    if (idx >= NN*CIN) return;
    int n = idx >> 4, o = idx & 15;
    float x0r = 0.f, re1 = 0.f, im1 = 0.f;
    #pragma unroll
    for (int i = 0; i < CIN; i++) {
        float a0 = x[(0*NN + n)*CIN + i];
        float a1 = x[(1*NN + n)*CIN + i];
        float a2 = x[(2*NN + n)*CIN + i];
        float a3 = x[(3*NN + n)*CIN + i];
        float S = a0 + a1 + a2 + a3;
        float P = a0 - a2;
        float Q = a3 - a1;
        float wrv = sWr[i][o], wiv = sWi[i][o];
        x0r += S * wrv;
        re1 += P * wrv - Q * wiv;
        im1 += P * wiv + Q * wrv;
    }
    g_xnew[(0*NN + n)*CIN + o] = 0.25f*(x0r + 2.f*re1);
    g_xnew[(1*NN + n)*CIN + o] = 0.25f*(x0r - 2.f*im1);
    g_xnew[(2*NN + n)*CIN + o] = 0.25f*(x0r - 2.f*re1);
    g_xnew[(3*NN + n)*CIN + o] = 0.25f*(x0r + 2.f*im1);
}

// ---------------- per-node in-degree -----------------------------------------
__global__ void count_kernel(const int* __restrict__ eidx) {
    int e = blockIdx.x * blockDim.x + threadIdx.x;
    if (e < EE) atomicAdd(&g_cnt[eidx[EE + e]], 1.0f);
}

// ---------------- helpers -----------------------------------------------------
__device__ __forceinline__ void mma_f16(float* c, const unsigned* a, const unsigned* b) {
    asm volatile(
        "mma.sync.aligned.m16n8k16.row.col.f32.f16.f16.f32 "
        "{%0,%1,%2,%3}, {%4,%5,%6,%7}, {%8,%9}, {%0,%1,%2,%3};\n"
        : "+f"(c[0]), "+f"(c[1]), "+f"(c[2]), "+f"(c[3])
        : "r"(a[0]), "r"(a[1]), "r"(a[2]), "r"(a[3]), "r"(b[0]), "r"(b[1]));
}
__device__ __forceinline__ void ldmat4(unsigned* a, const __half* p) {
    unsigned addr = (unsigned)__cvta_generic_to_shared(p);
    asm volatile("ldmatrix.sync.aligned.m8n8.x4.shared.b16 {%0,%1,%2,%3}, [%4];"
                 : "=r"(a[0]), "=r"(a[1]), "=r"(a[2]), "=r"(a[3]) : "r"(addr));
}
__device__ __forceinline__ unsigned packh2(float a, float b) {
    __half2 t;
    t.x = __float2half_rn(a);
    t.y = __float2half_rn(b);
    return *reinterpret_cast<unsigned*>(&t);
}
__device__ __forceinline__ void cpa16(void* dst, const void* src) {
    unsigned d = (unsigned)__cvta_generic_to_shared(dst);
    asm volatile("cp.async.cg.shared.global [%0], [%1], 16;" :: "r"(d), "l"(src));
}
#define CP_COMMIT asm volatile("cp.async.commit_group;")
#define CP_WAIT0  asm volatile("cp.async.wait_group 0;" ::: "memory")

// single-term fp16 GEMM (proven R9): acc += A@W^T  (M=128, N=128, K=128)
__device__ __forceinline__ void gemm_f16(
    const __half* __restrict__ sA, const __half* __restrict__ sW,
    int warp, int lane, float acc[8][2][4])
{
    const __half* Arow = sA + (lane & 15)*KPAD + (lane >> 4)*8;
    const __half* Wb = sW + (warp*16 + (lane >> 2))*KPAD + (lane & 3)*2;
    #pragma unroll
    for (int k0 = 0; k0 < 128; k0 += 16) {
        unsigned b0[2], b1[2];
        b0[0] = *(const unsigned*)&Wb[k0];
        b0[1] = *(const unsigned*)&Wb[k0 + 8];
        b1[0] = *(const unsigned*)&Wb[8*KPAD + k0];
        b1[1] = *(const unsigned*)&Wb[8*KPAD + k0 + 8];
        #pragma unroll
        for (int mt = 0; mt < 8; mt++) {
            unsigned a[4];
            ldmat4(a, Arow + mt*16*KPAD + k0);
            mma_f16(acc[mt][0], a, b0);
            mma_f16(acc[mt][1], a, b1);
        }
    }
}

// ---------------- fused: GEMM1 + relu + GEMM2 + message + scatter ------------
__global__ __launch_bounds__(256, 2)
void fused_kernel(const float* __restrict__ ea,  const float* __restrict__ b1g,
                  const float* __restrict__ b2g, const int* __restrict__ eidx,
                  const float* __restrict__ esh)
{
    extern __shared__ char smem_raw[];
    __half* sA  = (__half*)(smem_raw + OFF_A);     // 128 x KPAD fp16
    __half* sW  = (__half*)(smem_raw + OFF_W);     // 128 x KPAD fp16
    __half* sEw = (__half*)(smem_raw + OFF_EW);    // 128 x EWP fp16

    const int tid  = threadIdx.x;
    const int warp = tid >> 5, lane = tid & 31;
    const int row0 = blockIdx.x * 128;

    // ---- prefetch W1 via cp.async (overlaps A gather) ----
    #pragma unroll
    for (int t = 0; t < 8; t++) {
        int idx = tid + t * 256;
        int n = idx >> 4, q = (idx & 15) << 3;
        cpa16(&sW[n*KPAD + q], &g_w1t[n*NF + q]);
    }
    CP_COMMIT;

    // ---- load A tile (128x128 f32 -> fp16) ----
    #pragma unroll
    for (int t = 0; t < 16; t++) {
        int idx = tid + t * 256;           // 0..4095 float4s
        int r = idx >> 5, q = (idx & 31) << 2;
        float4 v = *(const float4*)&ea[(size_t)(row0 + r)*NF + q];
        uint2 u = make_uint2(packh2(v.x, v.y), packh2(v.z, v.w));
        *(uint2*)&sA[r*KPAD + q] = u;
    }
    CP_WAIT0;
    __syncthreads();

    // ---- GEMM1: H = relu(A@W1 + b1) ----
    float acc[8][2][4];
    {
        int colb = warp*16 + (lane & 3)*2;
        #pragma unroll
        for (int nt = 0; nt < 2; nt++) {
            float bc0 = b1g[colb + nt*8], bc1 = b1g[colb + nt*8 + 1];
            #pragma unroll
            for (int mt = 0; mt < 8; mt++) {
                acc[mt][nt][0] = bc0; acc[mt][nt][1] = bc1;
                acc[mt][nt][2] = bc0; acc[mt][nt][3] = bc1;
            }
        }
    }
    gemm_f16(sA, sW, warp, lane, acc);
    __syncthreads();   // done reading sA and sW

    // ---- prefetch W2 chunk 0 (overlaps re-split + metadata) ----
    #pragma unroll
    for (int t = 0; t < 8; t++) {
        int idx = tid + t * 256;
        int n = idx >> 4, q = (idx & 15) << 3;
        cpa16(&sW[n*KPAD + q], &g_w2t[n*NF + q]);
    }
    CP_COMMIT;

    // ---- relu -> fp16 H back into sA ----
    {
        int c0 = warp*16 + (lane & 3)*2;
        int r0 = lane >> 2;
        #pragma unroll
        for (int mt = 0; mt < 8; mt++) {
            #pragma unroll
            for (int nt = 0; nt < 2; nt++) {
                int col = c0 + nt*8;
                #pragma unroll
                for (int half = 0; half < 2; half++) {
                    int row = mt*16 + r0 + half*8;
                    float h0 = fmaxf(acc[mt][nt][half*2 + 0], 0.f);
                    float h1 = fmaxf(acc[mt][nt][half*2 + 1], 0.f);
                    *(unsigned*)&sA[row*KPAD + col] = packh2(h0, h1);
                }
            }
        }
    }

    // ---- per-edge metadata (2 threads per row) ----
    const int r_e = tid >> 1, l = tid & 1;
    const int grow = row0 + r_e;
    const int b = grow / EE;
    const int e = grow - b*EE;
    const int src = eidx[e];
    const int dst = eidx[EE + e];
    const float4 sh = *(const float4*)&esh[(size_t)grow*4];
    float xg[CIN];
    {
        const float4* xgp = (const float4*)&g_xnew[((size_t)b*NN + src)*CIN];
        #pragma unroll
        for (int t4 = 0; t4 < 4; t4++) {
            float4 v = xgp[t4];
            xg[t4*4+0] = v.x; xg[t4*4+1] = v.y; xg[t4*4+2] = v.z; xg[t4*4+3] = v.w;
        }
    }
    float o0[8] = {0,0,0,0,0,0,0,0};
    float d1[4] = {0,0,0,0};

    CP_WAIT0;
    __syncthreads();   // H visible + W2 ch0 staged

    // ---- GEMM2 in 3 N-chunks of 128, fused message contraction ----
    #pragma unroll 1
    for (int ch = 0; ch < 3; ch++) {
        {
            int colb = ch*128 + warp*16 + (lane & 3)*2;
            #pragma unroll
            for (int nt = 0; nt < 2; nt++) {
                float bc0 = b2g[colb + nt*8], bc1 = b2g[colb + nt*8 + 1];
                #pragma unroll
                for (int mt = 0; mt < 8; mt++) {
                    acc[mt][nt][0] = bc0; acc[mt][nt][1] = bc1;
                    acc[mt][nt][2] = bc0; acc[mt][nt][3] = bc1;
                }
            }
        }
        gemm_f16(sA, sW, warp, lane, acc);
        __syncthreads();   // done reading sW; prev contraction long done

        // prefetch next W2 chunk into sW (overlaps sEw write + contraction)
        if (ch < 2) {
            #pragma unroll
            for (int t = 0; t < 8; t++) {
                int idx = tid + t * 256;
                int n = idx >> 4, q = (idx & 15) << 3;
                cpa16(&sW[n*KPAD + q], &g_w2t[(size_t)((ch+1)*128 + n)*NF + q]);
            }
            CP_COMMIT;
        }

        // write acc -> sEw (packed fp16)
        {
            int c0 = warp*16 + (lane & 3)*2;
            int r0 = lane >> 2;
            #pragma unroll
            for (int mt = 0; mt < 8; mt++) {
                #pragma unroll
                for (int nt = 0; nt < 2; nt++) {
                    int col = c0 + nt*8;
                    *(unsigned*)&sEw[(mt*16 + r0    )*EWP + col] =
                        packh2(acc[mt][nt][0], acc[mt][nt][1]);
                    *(unsigned*)&sEw[(mt*16 + r0 + 8)*EWP + col] =
                        packh2(acc[mt][nt][2], acc[mt][nt][3]);
                }
            }
        }
        __syncthreads();

        // message partial accumulation from this ew chunk (half2 reads)
        const __half2* er2 = (const __half2*)&sEw[r_e*EWP];
        if (ch == 0) {
            #pragma unroll
            for (int op = 0; op < 4; op++) {
                #pragma unroll
                for (int i = 0; i < 8; i++) {
                    float2 f = __half22float2(er2[i*8 + l*4 + op]);
                    o0[op*2]     += xg[i] * f.x;
                    o0[op*2 + 1] += xg[i] * f.y;
                }
            }
        } else if (ch == 1) {
            #pragma unroll
            for (int op = 0; op < 4; op++) {
                #pragma unroll
                for (int i = 0; i < 8; i++) {
                    float2 f = __half22float2(er2[i*8 + l*4 + op]);
                    o0[op*2]     += xg[i+8] * f.x;
                    o0[op*2 + 1] += xg[i+8] * f.y;
                }
            }
        } else {
            #pragma unroll
            for (int op = 0; op < 2; op++) {
                #pragma unroll
                for (int i = 0; i < 16; i++) {
                    float2 f = __half22float2(er2[i*4 + l*2 + op]);
                    d1[op*2]     += xg[i] * f.x;
                    d1[op*2 + 1] += xg[i] * f.y;
                }
            }
        }
        if (ch < 2) { CP_WAIT0; }
        __syncthreads();   // contraction done; sW ready for next chunk
    }

    // ---- scatter ----
    float* aggp = &g_agg[((size_t)b*NN + dst)*OUTD];
    float s0 = ALPHA_C * sh.x;
    #pragma unroll
    for (int oi = 0; oi < 8; oi++)
        atomicAdd(&aggp[l*8 + oi], s0 * o0[oi]);
    #pragma unroll
    for (int oi = 0; oi < 4; oi++) {
        int cch = l*4 + oi;
        float v = ALPHA_C * d1[oi];
        atomicAdd(&aggp[16 + cch*3 + 0], v * sh.y);
        atomicAdd(&aggp[16 + cch*3 + 1], v * sh.z);
        atomicAdd(&aggp[16 + cch*3 + 2], v * sh.w);
    }
}

// ---------------- mean-by-count + BN stats (proven) --------------------------
__global__ void stats_kernel() {
    int row = blockIdx.x * blockDim.x + threadIdx.x;
    float v[OUTD];
    if (row < BB*NN) {
        int n = row % NN;
        float inv = 1.0f / fmaxf(g_cnt[n], 1.0f);
        float4* p = (float4*)&g_agg[row*OUTD];
        #pragma unroll
        for (int t = 0; t < 10; t++) {
            float4 a = p[t];
            a.x *= inv; a.y *= inv; a.z *= inv; a.w *= inv;
            p[t] = a;
            v[t*4+0] = a.x; v[t*4+1] = a.y; v[t*4+2] = a.z; v[t*4+3] = a.w;
        }
    } else {
        #pragma unroll
        for (int c = 0; c < OUTD; c++) v[c] = 0.f;
    }
    #pragma unroll
    for (int c = 0; c < OUTD; c++) {
        float s = v[c], q = v[c]*v[c];
        #pragma unroll
        for (int off = 16; off > 0; off >>= 1) {
            s += __shfl_down_sync(0xffffffffu, s, off);
            q += __shfl_down_sync(0xffffffffu, q, off);
        }
        if ((threadIdx.x & 31) == 0) {
            atomicAdd(&g_sum[c],   s);
            atomicAdd(&g_sumsq[c], q);
        }
    }
}

__global__ void norm_kernel(float* __restrict__ out,
                            const float* __restrict__ gamma,
                            const float* __restrict__ beta) {
    int i = blockIdx.x * blockDim.x + threadIdx.x;
    if (i >= BB*NN*OUTD) return;
    int c = i % OUTD;
    const float invM = 1.0f / M_TOT;
    float mu  = g_sum[c] * invM;
    float var = g_sumsq[c] * invM - mu*mu;
    out[i] = (g_agg[i] - mu) * rsqrtf(var + BN_EPS_C) * gamma[c] + beta[c];
}

// ---------------- launch ------------------------------------------------------
extern "C" void kernel_launch(void* const* d_in, const int* in_sizes, int n_in,
                              void* d_out, int out_size) {
    const float* x     = (const float*)d_in[0];
    const int*   eidx  = (const int*)  d_in[1];
    const float* ea    = (const float*)d_in[2];
    const float* esh   = (const float*)d_in[3];
    const float* wr    = (const float*)d_in[4];
    const float* wi    = (const float*)d_in[5];
    const float* w1    = (const float*)d_in[6];
    const float* b1    = (const float*)d_in[7];
    const float* w2    = (const float*)d_in[8];
    const float* b2    = (const float*)d_in[9];
    const float* gamma = (const float*)d_in[10];
    const float* beta  = (const float*)d_in[11];
    float* out = (float*)d_out;

    cudaFuncSetAttribute(fused_kernel,
                         cudaFuncAttributeMaxDynamicSharedMemorySize, SMEM_BYTES);

    zero_kernel <<<(BB*NN*OUTD + 255)/256, 256>>>();
    xnew_kernel <<<(NN*CIN + 255)/256, 256>>>(x, wr, wi);
    count_kernel<<<(EE + 255)/256, 256>>>(eidx);
    prep_kernel <<<(WN*NF + 255)/256, 256>>>(w1, w2);
    fused_kernel<<<MROWS/128, 256, SMEM_BYTES>>>(ea, b1, b2, eidx, esh);
    stats_kernel<<<(BB*NN + 255)/256, 256>>>();
    norm_kernel <<<(BB*NN*OUTD + 255)/256, 256>>>(out, gamma, beta);
}

// round 15
// speedup vs baseline: 1.6427x; 1.1307x over previous
#include <cuda_runtime.h>
#include <cuda_fp16.h>
#include <math.h>

#define BB   4
#define NN   10000
#define EE   100000
#define CIN  16
#define NF   128
#define WN   384
#define OUTD 40
#define MROWS (BB*EE)            // 400000
#define ALPHA_C 0.25f
#define BN_EPS_C 1e-5f
#define M_TOT 40000.0f
#define KPAD 136                 // fp16 smem row stride (272B, ldmatrix conflict-free)
#define EWP  134                 // fp16 sEw row stride (halfs)
#define OFF_A  0                 // 128*KPAD halfs = 34816 B
#define OFF_W  34816             // 128*KPAD halfs = 34816 B
#define OFF_EW 69632             // 128*EWP halfs = 34304 B
#define SMEM_BYTES 103936        // -> 2 CTAs/SM

// ---------------- device scratch ---------------------------------------------
__device__ float g_xnew[BB*NN*CIN];
__device__ float g_agg[BB*NN*OUTD];
__device__ float g_cnt[NN];
__device__ float g_sum[OUTD];
__device__ float g_sumsq[OUTD];
__device__ __align__(16) __half g_w1t[NF*NF];   // [n][k] transposed fp16
__device__ __align__(16) __half g_w2t[WN*NF];   // [n][k] transposed fp16

// ---------------- init: zero scratch + weight prep + FFT time mixing ---------
// All tasks are independent writes; fused to cut launch count.
__global__ void init_kernel(const float* __restrict__ x,
                            const float* __restrict__ wr,
                            const float* __restrict__ wi,
                            const float* __restrict__ w1,
                            const float* __restrict__ w2) {
    __shared__ float sWr[CIN][CIN];
    __shared__ float sWi[CIN][CIN];
    int t = threadIdx.x;
    {   // sum over MODES=2: tc_w* shape (16,16,2)
        int i = t >> 4, o = t & 15;
        sWr[i][o] = wr[i*32 + o*2 + 0] + wr[i*32 + o*2 + 1];
        sWi[i][o] = wi[i*32 + o*2 + 0] + wi[i*32 + o*2 + 1];
    }
    __syncthreads();
    int idx = blockIdx.x * blockDim.x + t;

    if (idx < BB*NN*OUTD) g_agg[idx] = 0.0f;
    if (idx < NN)         g_cnt[idx] = 0.0f;
    if (idx < OUTD) { g_sum[idx] = 0.0f; g_sumsq[idx] = 0.0f; }
    if (idx < NF*NF) {
        int n = idx / NF, k = idx % NF;
        g_w1t[idx] = __float2half_rn(w1[k*NF + n]);
    }
    if (idx < WN*NF) {
        int n = idx / NF, k = idx % NF;
        g_w2t[idx] = __float2half_rn(w2[k*WN + n]);
    }
    if (idx < NN*CIN) {
        int n = idx >> 4, o = idx & 15;
        float x0r = 0.f, re1 = 0.f, im1 = 0.f;
        #pragma unroll
        for (int i = 0; i < CIN; i++) {
            float a0 = x[(0*NN + n)*CIN + i];
            float a1 = x[(1*NN + n)*CIN + i];
            float a2 = x[(2*NN + n)*CIN + i];
            float a3 = x[(3*NN + n)*CIN + i];
            float S = a0 + a1 + a2 + a3;
            float P = a0 - a2;
            float Q = a3 - a1;
            float wrv = sWr[i][o], wiv = sWi[i][o];
            x0r += S * wrv;
            re1 += P * wrv - Q * wiv;
            im1 += P * wiv + Q * wrv;
        }
        g_xnew[(0*NN + n)*CIN + o] = 0.25f*(x0r + 2.f*re1);
        g_xnew[(1*NN + n)*CIN + o] = 0.25f*(x0r - 2.f*im1);
        g_xnew[(2*NN + n)*CIN + o] = 0.25f*(x0r - 2.f*re1);
        g_xnew[(3*NN + n)*CIN + o] = 0.25f*(x0r + 2.f*im1);
    }
}

// ---------------- per-node in-degree (after init zeroes g_cnt) ---------------
__global__ void count_kernel(const int* __restrict__ eidx) {
    int e = blockIdx.x * blockDim.x + threadIdx.x;
    if (e < EE) atomicAdd(&g_cnt[eidx[EE + e]], 1.0f);
}

// ---------------- helpers -----------------------------------------------------
__device__ __forceinline__ void mma_f16(float* c, const unsigned* a, const unsigned* b) {
    asm volatile(
        "mma.sync.aligned.m16n8k16.row.col.f32.f16.f16.f32 "
        "{%0,%1,%2,%3}, {%4,%5,%6,%7}, {%8,%9}, {%0,%1,%2,%3};\n"
        : "+f"(c[0]), "+f"(c[1]), "+f"(c[2]), "+f"(c[3])
        : "r"(a[0]), "r"(a[1]), "r"(a[2]), "r"(a[3]), "r"(b[0]), "r"(b[1]));
}
__device__ __forceinline__ void ldmat4(unsigned* a, const __half* p) {
    unsigned addr = (unsigned)__cvta_generic_to_shared(p);
    asm volatile("ldmatrix.sync.aligned.m8n8.x4.shared.b16 {%0,%1,%2,%3}, [%4];"
                 : "=r"(a[0]), "=r"(a[1]), "=r"(a[2]), "=r"(a[3]) : "r"(addr));
}
__device__ __forceinline__ unsigned packh2(float a, float b) {
    __half2 t;
    t.x = __float2half_rn(a);
    t.y = __float2half_rn(b);
    return *reinterpret_cast<unsigned*>(&t);
}
__device__ __forceinline__ void cpa16(void* dst, const void* src) {
    unsigned d = (unsigned)__cvta_generic_to_shared(dst);
    asm volatile("cp.async.cg.shared.global [%0], [%1], 16;" :: "r"(d), "l"(src));
}
#define CP_COMMIT asm volatile("cp.async.commit_group;")
#define CP_WAIT0  asm volatile("cp.async.wait_group 0;" ::: "memory")

// single-term fp16 GEMM (proven R9): acc += A@W^T  (M=128, N=128, K=128)
__device__ __forceinline__ void gemm_f16(
    const __half* __restrict__ sA, const __half* __restrict__ sW,
    int warp, int lane, float acc[8][2][4])
{
    const __half* Arow = sA + (lane & 15)*KPAD + (lane >> 4)*8;
    const __half* Wb = sW + (warp*16 + (lane >> 2))*KPAD + (lane & 3)*2;
    #pragma unroll
    for (int k0 = 0; k0 < 128; k0 += 16) {
        unsigned b0[2], b1[2];
        b0[0] = *(const unsigned*)&Wb[k0];
        b0[1] = *(const unsigned*)&Wb[k0 + 8];
        b1[0] = *(const unsigned*)&Wb[8*KPAD + k0];
        b1[1] = *(const unsigned*)&Wb[8*KPAD + k0 + 8];
        #pragma unroll
        for (int mt = 0; mt < 8; mt++) {
            unsigned a[4];
            ldmat4(a, Arow + mt*16*KPAD + k0);
            mma_f16(acc[mt][0], a, b0);
            mma_f16(acc[mt][1], a, b1);
        }
    }
}

// ---------------- fused: GEMM1 + relu + GEMM2 + message + scatter ------------
// (unchanged from R14 winner)
__global__ __launch_bounds__(256, 2)
void fused_kernel(const float* __restrict__ ea,  const float* __restrict__ b1g,
                  const float* __restrict__ b2g, const int* __restrict__ eidx,
                  const float* __restrict__ esh)
{
    extern __shared__ char smem_raw[];
    __half* sA  = (__half*)(smem_raw + OFF_A);     // 128 x KPAD fp16
    __half* sW  = (__half*)(smem_raw + OFF_W);     // 128 x KPAD fp16
    __half* sEw = (__half*)(smem_raw + OFF_EW);    // 128 x EWP fp16

    const int tid  = threadIdx.x;
    const int warp = tid >> 5, lane = tid & 31;
    const int row0 = blockIdx.x * 128;

    // ---- prefetch W1 via cp.async (overlaps A gather) ----
    #pragma unroll
    for (int t = 0; t < 8; t++) {
        int idx = tid + t * 256;
        int n = idx >> 4, q = (idx & 15) << 3;
        cpa16(&sW[n*KPAD + q], &g_w1t[n*NF + q]);
    }
    CP_COMMIT;

    // ---- load A tile (128x128 f32 -> fp16) ----
    #pragma unroll
    for (int t = 0; t < 16; t++) {
        int idx = tid + t * 256;           // 0..4095 float4s
        int r = idx >> 5, q = (idx & 31) << 2;
        float4 v = *(const float4*)&ea[(size_t)(row0 + r)*NF + q];
        uint2 u = make_uint2(packh2(v.x, v.y), packh2(v.z, v.w));
        *(uint2*)&sA[r*KPAD + q] = u;
    }
    CP_WAIT0;
    __syncthreads();

    // ---- GEMM1: H = relu(A@W1 + b1) ----
    float acc[8][2][4];
    {
        int colb = warp*16 + (lane & 3)*2;
        #pragma unroll
        for (int nt = 0; nt < 2; nt++) {
            float bc0 = b1g[colb + nt*8], bc1 = b1g[colb + nt*8 + 1];
            #pragma unroll
            for (int mt = 0; mt < 8; mt++) {
                acc[mt][nt][0] = bc0; acc[mt][nt][1] = bc1;
                acc[mt][nt][2] = bc0; acc[mt][nt][3] = bc1;
            }
        }
    }
    gemm_f16(sA, sW, warp, lane, acc);
    __syncthreads();   // done reading sA and sW

    // ---- prefetch W2 chunk 0 (overlaps re-split + metadata) ----
    #pragma unroll
    for (int t = 0; t < 8; t++) {
        int idx = tid + t * 256;
        int n = idx >> 4, q = (idx & 15) << 3;
        cpa16(&sW[n*KPAD + q], &g_w2t[n*NF + q]);
    }
    CP_COMMIT;

    // ---- relu -> fp16 H back into sA ----
    {
        int c0 = warp*16 + (lane & 3)*2;
        int r0 = lane >> 2;
        #pragma unroll
        for (int mt = 0; mt < 8; mt++) {
            #pragma unroll
            for (int nt = 0; nt < 2; nt++) {
                int col = c0 + nt*8;
                #pragma unroll
                for (int half = 0; half < 2; half++) {
                    int row = mt*16 + r0 + half*8;
                    float h0 = fmaxf(acc[mt][nt][half*2 + 0], 0.f);
                    float h1 = fmaxf(acc[mt][nt][half*2 + 1], 0.f);
                    *(unsigned*)&sA[row*KPAD + col] = packh2(h0, h1);
                }
            }
        }
    }

    // ---- per-edge metadata (2 threads per row) ----
    const int r_e = tid >> 1, l = tid & 1;
    const int grow = row0 + r_e;
    const int b = grow / EE;
    const int e = grow - b*EE;
    const int src = eidx[e];
    const int dst = eidx[EE + e];
    const float4 sh = *(const float4*)&esh[(size_t)grow*4];
    float xg[CIN];
    {
        const float4* xgp = (const float4*)&g_xnew[((size_t)b*NN + src)*CIN];
        #pragma unroll
        for (int t4 = 0; t4 < 4; t4++) {
            float4 v = xgp[t4];
            xg[t4*4+0] = v.x; xg[t4*4+1] = v.y; xg[t4*4+2] = v.z; xg[t4*4+3] = v.w;
        }
    }
    float o0[8] = {0,0,0,0,0,0,0,0};
    float d1[4] = {0,0,0,0};

    CP_WAIT0;
    __syncthreads();   // H visible + W2 ch0 staged

    // ---- GEMM2 in 3 N-chunks of 128, fused message contraction ----
    #pragma unroll 1
    for (int ch = 0; ch < 3; ch++) {
        {
            int colb = ch*128 + warp*16 + (lane & 3)*2;
            #pragma unroll
            for (int nt = 0; nt < 2; nt++) {
                float bc0 = b2g[colb + nt*8], bc1 = b2g[colb + nt*8 + 1];
                #pragma unroll
                for (int mt = 0; mt < 8; mt++) {
                    acc[mt][nt][0] = bc0; acc[mt][nt][1] = bc1;
                    acc[mt][nt][2] = bc0; acc[mt][nt][3] = bc1;
                }
            }
        }
        gemm_f16(sA, sW, warp, lane, acc);
        __syncthreads();   // done reading sW; prev contraction long done

        // prefetch next W2 chunk into sW (overlaps sEw write + contraction)
        if (ch < 2) {
            #pragma unroll
            for (int t = 0; t < 8; t++) {
                int idx = tid + t * 256;
                int n = idx >> 4, q = (idx & 15) << 3;
                cpa16(&sW[n*KPAD + q], &g_w2t[(size_t)((ch+1)*128 + n)*NF + q]);
            }
            CP_COMMIT;
        }

        // write acc -> sEw (packed fp16)
        {
            int c0 = warp*16 + (lane & 3)*2;
            int r0 = lane >> 2;
            #pragma unroll
            for (int mt = 0; mt < 8; mt++) {
                #pragma unroll
                for (int nt = 0; nt < 2; nt++) {
                    int col = c0 + nt*8;
                    *(unsigned*)&sEw[(mt*16 + r0    )*EWP + col] =
                        packh2(acc[mt][nt][0], acc[mt][nt][1]);
                    *(unsigned*)&sEw[(mt*16 + r0 + 8)*EWP + col] =
                        packh2(acc[mt][nt][2], acc[mt][nt][3]);
                }
            }
        }
        __syncthreads();

        // message partial accumulation from this ew chunk (half2 reads)
        const __half2* er2 = (const __half2*)&sEw[r_e*EWP];
        if (ch == 0) {
            #pragma unroll
            for (int op = 0; op < 4; op++) {
                #pragma unroll
                for (int i = 0; i < 8; i++) {
                    float2 f = __half22float2(er2[i*8 + l*4 + op]);
                    o0[op*2]     += xg[i] * f.x;
                    o0[op*2 + 1] += xg[i] * f.y;
                }
            }
        } else if (ch == 1) {
            #pragma unroll
            for (int op = 0; op < 4; op++) {
                #pragma unroll
                for (int i = 0; i < 8; i++) {
                    float2 f = __half22float2(er2[i*8 + l*4 + op]);
                    o0[op*2]     += xg[i+8] * f.x;
                    o0[op*2 + 1] += xg[i+8] * f.y;
                }
            }
        } else {
            #pragma unroll
            for (int op = 0; op < 2; op++) {
                #pragma unroll
                for (int i = 0; i < 16; i++) {
                    float2 f = __half22float2(er2[i*4 + l*2 + op]);
                    d1[op*2]     += xg[i] * f.x;
                    d1[op*2 + 1] += xg[i] * f.y;
                }
            }
        }
        if (ch < 2) { CP_WAIT0; }
        __syncthreads();   // contraction done; sW ready for next chunk
    }

    // ---- scatter ----
    float* aggp = &g_agg[((size_t)b*NN + dst)*OUTD];
    float s0 = ALPHA_C * sh.x;
    #pragma unroll
    for (int oi = 0; oi < 8; oi++)
        atomicAdd(&aggp[l*8 + oi], s0 * o0[oi]);
    #pragma unroll
    for (int oi = 0; oi < 4; oi++) {
        int cch = l*4 + oi;
        float v = ALPHA_C * d1[oi];
        atomicAdd(&aggp[16 + cch*3 + 0], v * sh.y);
        atomicAdd(&aggp[16 + cch*3 + 1], v * sh.z);
        atomicAdd(&aggp[16 + cch*3 + 2], v * sh.w);
    }
}

// ---------------- mean-by-count + BN stats (4 rows per thread) ---------------
#define SROWS 4
#define STHREADS 10240           // 40 blocks x 256
__global__ void stats_kernel() {
    int t0 = blockIdx.x * blockDim.x + threadIdx.x;   // 0..10239
    float s[OUTD], q[OUTD];
    #pragma unroll
    for (int c = 0; c < OUTD; c++) { s[c] = 0.f; q[c] = 0.f; }
    #pragma unroll
    for (int j = 0; j < SROWS; j++) {
        int row = t0 + j*STHREADS;
        if (row < BB*NN) {
            int n = row % NN;
            float inv = 1.0f / fmaxf(g_cnt[n], 1.0f);
            float4* p = (float4*)&g_agg[row*OUTD];
            #pragma unroll
            for (int t = 0; t < 10; t++) {
                float4 a = p[t];
                a.x *= inv; a.y *= inv; a.z *= inv; a.w *= inv;
                p[t] = a;
                s[t*4+0] += a.x; q[t*4+0] += a.x*a.x;
                s[t*4+1] += a.y; q[t*4+1] += a.y*a.y;
                s[t*4+2] += a.z; q[t*4+2] += a.z*a.z;
                s[t*4+3] += a.w; q[t*4+3] += a.w*a.w;
            }
        }
    }
    #pragma unroll
    for (int c = 0; c < OUTD; c++) {
        float sv = s[c], qv = q[c];
        #pragma unroll
        for (int off = 16; off > 0; off >>= 1) {
            sv += __shfl_down_sync(0xffffffffu, sv, off);
            qv += __shfl_down_sync(0xffffffffu, qv, off);
        }
        if ((threadIdx.x & 31) == 0) {
            atomicAdd(&g_sum[c],   sv);
            atomicAdd(&g_sumsq[c], qv);
        }
    }
}

__global__ void norm_kernel(float* __restrict__ out,
                            const float* __restrict__ gamma,
                            const float* __restrict__ beta) {
    int i = blockIdx.x * blockDim.x + threadIdx.x;
    if (i >= BB*NN*OUTD) return;
    int c = i % OUTD;
    const float invM = 1.0f / M_TOT;
    float mu  = g_sum[c] * invM;
    float var = g_sumsq[c] * invM - mu*mu;
    out[i] = (g_agg[i] - mu) * rsqrtf(var + BN_EPS_C) * gamma[c] + beta[c];
}

// ---------------- launch ------------------------------------------------------
extern "C" void kernel_launch(void* const* d_in, const int* in_sizes, int n_in,
                              void* d_out, int out_size) {
    const float* x     = (const float*)d_in[0];
    const int*   eidx  = (const int*)  d_in[1];
    const float* ea    = (const float*)d_in[2];
    const float* esh   = (const float*)d_in[3];
    const float* wr    = (const float*)d_in[4];
    const float* wi    = (const float*)d_in[5];
    const float* w1    = (const float*)d_in[6];
    const float* b1    = (const float*)d_in[7];
    const float* w2    = (const float*)d_in[8];
    const float* b2    = (const float*)d_in[9];
    const float* gamma = (const float*)d_in[10];
    const float* beta  = (const float*)d_in[11];
    float* out = (float*)d_out;

    cudaFuncSetAttribute(fused_kernel,
                         cudaFuncAttributeMaxDynamicSharedMemorySize, SMEM_BYTES);

    init_kernel <<<(BB*NN*OUTD + 255)/256, 256>>>(x, wr, wi, w1, w2);
    count_kernel<<<(EE + 255)/256, 256>>>(eidx);
    fused_kernel<<<MROWS/128, 256, SMEM_BYTES>>>(ea, b1, b2, eidx, esh);
    stats_kernel<<<STHREADS/256, 256>>>();
    norm_kernel <<<(BB*NN*OUTD + 255)/256, 256>>>(out, gamma, beta);
}